// round 13
// baseline (speedup 1.0000x reference)
#include <cuda_runtime.h>
#include <stdint.h>

#define NROWS 500000
#define TPB   256
#define ROWS_PER_BLOCK 16     // 8 warps * 2 rows

template<class T> __device__ __forceinline__ T vmax(T a, T b) { return a > b ? a : b; }
template<class T> __device__ __forceinline__ T vmin(T a, T b) { return a < b ? a : b; }

// fixed-direction CE: first slot keeps max (descending)
template<class T> __device__ __forceinline__ void ceF(T& a, T& b) {
    T h = vmax(a, b), l = vmin(a, b); a = h; b = l;
}
// in-lane bitonic-4 merge (bitonic -> descending), all fixed
template<class T> __device__ __forceinline__ void bit4(T K[4]) {
    ceF(K[0], K[2]); ceF(K[1], K[3]);
    ceF(K[0], K[1]); ceF(K[2], K[3]);
}
// cross-lane straight CE at distance d, predicated
template<class T> __device__ __forceinline__ void crossK(T K[4], int d, bool km, unsigned m) {
    #pragma unroll
    for (int r = 0; r < 4; r++) {
        T q = __shfl_xor_sync(m, K[r], d);
        K[r] = km ? vmax(K[r], q) : vmin(K[r], q);
    }
}
// cross-lane reversed CE, predicated; reads ALL partners before writing
template<class T> __device__ __forceinline__ void crossRev(T K[4], int d, bool km, unsigned m) {
    T q0 = __shfl_xor_sync(m, K[3], d);
    T q1 = __shfl_xor_sync(m, K[2], d);
    T q2 = __shfl_xor_sync(m, K[1], d);
    T q3 = __shfl_xor_sync(m, K[0], d);
    K[0] = km ? vmax(K[0], q0) : vmin(K[0], q0);
    K[1] = km ? vmax(K[1], q1) : vmin(K[1], q1);
    K[2] = km ? vmax(K[2], q2) : vmin(K[2], q2);
    K[3] = km ? vmax(K[3], q3) : vmin(K[3], q3);
}
// cross-lane reversed prune: keep max BOTH sides; capture max of discarded mins.
// All partner values read before any write; mins use original K (R7 lesson).
template<class T, bool CAP>
__device__ __forceinline__ void crossRevMax(T K[4], int d, unsigned m, T& cap) {
    T q0 = __shfl_xor_sync(m, K[3], d);
    T q1 = __shfl_xor_sync(m, K[2], d);
    T q2 = __shfl_xor_sync(m, K[1], d);
    T q3 = __shfl_xor_sync(m, K[0], d);
    if (CAP) {
        cap = vmax(cap, vmin(K[0], q0));
        cap = vmax(cap, vmin(K[1], q1));
        cap = vmax(cap, vmin(K[2], q2));
        cap = vmax(cap, vmin(K[3], q3));
    }
    K[0] = vmax(K[0], q0);
    K[1] = vmax(K[1], q1);
    K[2] = vmax(K[2], q2);
    K[3] = vmax(K[3], q3);
}

// Top-16-of-64 sorted DESC. Input: lane (s = lane&15) holds elements 4s..4s+3.
// Output: every 4-lane subgroup holds sorted top-16; position p = 4*(lane&3) + r.
// cap accumulates the max over discarded elements (both prunes) for this lane.
template<class T, bool CAP>
__device__ __forceinline__ void top16net(T K[4], bool P1, bool P2, unsigned m, T& cap) {
    // in-lane sort-4 desc (all fixed-direction)
    ceF(K[0], K[1]); ceF(K[2], K[3]);
    ceF(K[0], K[2]); ceF(K[1], K[3]);
    ceF(K[1], K[2]);
    // merge lane pairs -> sorted-8
    crossRev(K, 1, P1, m);   bit4(K);
    // merge -> sorted-16 per 4-lane group
    crossRev(K, 3, P2, m);   crossK(K, 1, P1, m);   bit4(K);
    // merge two sorted-16s across xor7, prune to top-16, re-sort
    crossRevMax<T,CAP>(K, 7, m, cap);
    crossK(K, 2, P2, m);     crossK(K, 1, P1, m);   bit4(K);
    // same across xor11 -> top-16 of 64
    crossRevMax<T,CAP>(K, 11, m, cap);
    crossK(K, 2, P2, m);     crossK(K, 1, P1, m);   bit4(K);
}

__device__ __forceinline__ unsigned norm_key(float a, float b, float c, unsigned tag) {
    float n = __fadd_rn(__fadd_rn(__fmul_rn(a, a), __fmul_rn(b, b)), __fmul_rn(c, c));
    return (__float_as_uint(n) & 0xFFFFFFC0u) | tag;
}

// gather one 3-float vector: 1 LDG.64 + 1 LDG.32 (8B-aligned split by parity)
__device__ __forceinline__ void gather_vec(const float* __restrict__ xrow, int idx,
                                           float& a, float& b, float& c) {
    bool odd = (idx & 1);
    int e = 3 * idx + (odd ? 1 : 0);
    int o = odd ? 3 * idx : 3 * idx + 2;
    float2 f2 = *(const float2*)(xrow + e);
    float  f1 = xrow[o];
    a = odd ? f1   : f2.x;
    b = odd ? f2.x : f2.y;
    c = odd ? f2.y : f1;
}

// store one 3-float vector at position p: 1 STG.64 + 1 STG.32 (parity split)
__device__ __forceinline__ void store_vec(float* __restrict__ orow, int p,
                                          float a, float b, float c) {
    bool odd = (p & 1);
    int e = 3 * p + (odd ? 1 : 0);
    int o = odd ? 3 * p : 3 * p + 2;
    float2 f2 = odd ? make_float2(b, c) : make_float2(a, b);
    float  f1 = odd ? a : c;
    *(float2*)(orow + e) = f2;
    orow[o] = f1;
}

__global__ __launch_bounds__(TPB, 8)
void vns_kernel(const float* __restrict__ x, float* __restrict__ out) {
    const int lane = threadIdx.x & 31;
    const int s    = lane & 15;                        // sublane within row
    const int row  = blockIdx.x * ROWS_PER_BLOCK + (threadIdx.x >> 5) * 2 + (lane >> 4);
    const bool P1  = (lane & 1) == 0;
    const bool P2  = (lane & 2) == 0;
    const unsigned hm = 0xFFFFu << (lane & 16);        // half-warp (row) mask

    // ---- load 3 CONSECUTIVE float4 per lane (48B stride across lanes) ----
    const float* __restrict__ xrow = x + (size_t)row * 192;
    const float4* p4 = (const float4*)xrow + 3 * s;
    const unsigned b63 = 63 - 4 * s;
    unsigned K[4];
    {
        float4 r0 = p4[0], r1 = p4[1], r2 = p4[2];
        K[0] = norm_key(r0.x, r0.y, r0.z, b63    );
        K[1] = norm_key(r0.w, r1.x, r1.y, b63 - 1);
        K[2] = norm_key(r1.z, r1.w, r2.x, b63 - 2);
        K[3] = norm_key(r2.y, r2.z, r2.w, b63 - 3);
    }

    unsigned cap = 0;
    top16net<unsigned, true>(K, P1, P2, 0xffffffffu, cap);
    // key16 = true 17th-largest trunc-key: max of all discarded over the 16-lane group
    unsigned key16 = cap;
    key16 = vmax(key16, __shfl_xor_sync(0xffffffffu, key16, 1));
    key16 = vmax(key16, __shfl_xor_sync(0xffffffffu, key16, 2));
    key16 = vmax(key16, __shfl_xor_sync(0xffffffffu, key16, 4));
    key16 = vmax(key16, __shfl_xor_sync(0xffffffffu, key16, 8));

    // ---- exactness checks: adjacent trunc-equal over sorted positions 0..16 ----
    unsigned nk = __shfl_down_sync(0xffffffffu, K[0], 1);  // next lane's first position
    bool last = ((lane & 3) == 3);
    unsigned bcmp = last ? key16 : nk;                     // pos15 vs key16, else pos 4j+3 vs 4j+4
    bool bad = (((K[0] ^ K[1]) >> 6) == 0) ||
               (((K[1] ^ K[2]) >> 6) == 0) ||
               (((K[2] ^ K[3]) >> 6) == 0) ||
               (((K[3] ^ bcmp) >> 6) == 0);
    unsigned bal = __ballot_sync(0xffffffffu, bad);
    bool rowBad = ((bal >> (lane & 16)) & 0xFFFFu) != 0;

    float* __restrict__ orow = out + (size_t)row * 48;
    const int g2 = (lane >> 2) & 3;
    const int p  = 4 * (lane & 3) + g2;                    // my output position

    if (!rowBad) {
        // ---- fast path: position p's key from own registers ----
        unsigned t0 = (g2 & 1) ? K[1] : K[0];
        unsigned t1 = (g2 & 1) ? K[3] : K[2];
        unsigned Kp = (g2 & 2) ? t1 : t0;
        int idx = 63 - (int)(Kp & 63u);
        float a, b, c;
        gather_vec(xrow, idx, a, b, c);
        store_vec(orow, p, a, b, c);
    } else {
        // ---- exact fallback (rare, per-row uniform): 64-bit (norm, idx) keys ----
        unsigned long long A[4], dcap = 0;
        {
            float4 r0 = p4[0], r1 = p4[1], r2 = p4[2];
            float N0 = __fadd_rn(__fadd_rn(__fmul_rn(r0.x,r0.x), __fmul_rn(r0.y,r0.y)), __fmul_rn(r0.z,r0.z));
            float N1 = __fadd_rn(__fadd_rn(__fmul_rn(r0.w,r0.w), __fmul_rn(r1.x,r1.x)), __fmul_rn(r1.y,r1.y));
            float N2 = __fadd_rn(__fadd_rn(__fmul_rn(r1.z,r1.z), __fmul_rn(r1.w,r1.w)), __fmul_rn(r2.x,r2.x));
            float N3 = __fadd_rn(__fadd_rn(__fmul_rn(r2.y,r2.y), __fmul_rn(r2.z,r2.z)), __fmul_rn(r2.w,r2.w));
            A[0] = ((unsigned long long)__float_as_uint(N0) << 32) | (b63    );
            A[1] = ((unsigned long long)__float_as_uint(N1) << 32) | (b63 - 1);
            A[2] = ((unsigned long long)__float_as_uint(N2) << 32) | (b63 - 2);
            A[3] = ((unsigned long long)__float_as_uint(N3) << 32) | (b63 - 3);
        }
        top16net<unsigned long long, false>(A, P1, P2, hm, dcap);
        unsigned long long t0 = (g2 & 1) ? A[1] : A[0];
        unsigned long long t1 = (g2 & 1) ? A[3] : A[2];
        unsigned long long Kp = (g2 & 2) ? t1 : t0;
        int idx = 63 - (int)(Kp & 63ull);
        float a, b, c;
        gather_vec(xrow, idx, a, b, c);
        store_vec(orow, p, a, b, c);
    }
}

extern "C" void kernel_launch(void* const* d_in, const int* in_sizes, int n_in,
                              void* d_out, int out_size) {
    const float* x = (const float*)d_in[0];
    float* out = (float*)d_out;
    vns_kernel<<<NROWS / ROWS_PER_BLOCK, TPB>>>(x, out);
}

// round 15
// speedup vs baseline: 1.1451x; 1.1451x over previous
#include <cuda_runtime.h>
#include <stdint.h>

#define NROWS 500000
#define TPB   256
#define ROWS_PER_BLOCK 32     // 8 warps * 4 rows

template<class T> __device__ __forceinline__ T vmax(T a, T b) { return a > b ? a : b; }
template<class T> __device__ __forceinline__ T vmin(T a, T b) { return a < b ? a : b; }

template<class T> __device__ __forceinline__ void ceF(T& a, T& b) {
    T h = vmax(a, b), l = vmin(a, b); a = h; b = l;
}

// in-lane Batcher odd-even mergesort-8, descending (19 CEs, all fixed)
template<class T> __device__ __forceinline__ void sort8(T K[8]) {
    ceF(K[0],K[1]); ceF(K[2],K[3]); ceF(K[4],K[5]); ceF(K[6],K[7]);
    ceF(K[0],K[2]); ceF(K[1],K[3]); ceF(K[4],K[6]); ceF(K[5],K[7]);
    ceF(K[1],K[2]); ceF(K[5],K[6]);
    ceF(K[0],K[4]); ceF(K[1],K[5]); ceF(K[2],K[6]); ceF(K[3],K[7]);
    ceF(K[2],K[4]); ceF(K[3],K[5]);
    ceF(K[1],K[2]); ceF(K[3],K[4]); ceF(K[5],K[6]);
}

// in-lane bitonic merge-8 (bitonic -> sorted desc), 12 CEs fixed
template<class T> __device__ __forceinline__ void bmerge8(T K[8]) {
    ceF(K[0],K[4]); ceF(K[1],K[5]); ceF(K[2],K[6]); ceF(K[3],K[7]);
    ceF(K[0],K[2]); ceF(K[1],K[3]); ceF(K[4],K[6]); ceF(K[5],K[7]);
    ceF(K[0],K[1]); ceF(K[2],K[3]); ceF(K[4],K[5]); ceF(K[6],K[7]);
}

// cross-lane reversed CE, predicated; reads ALL partners before writing
template<class T> __device__ __forceinline__ void crossRevPred(T K[8], int d, bool km, unsigned m) {
    T q[8];
    #pragma unroll
    for (int r = 0; r < 8; r++) q[r] = __shfl_xor_sync(m, K[7 - r], d);
    #pragma unroll
    for (int r = 0; r < 8; r++) K[r] = km ? vmax(K[r], q[r]) : vmin(K[r], q[r]);
}

// cross-lane reversed prune: keep max both sides; capture max of discarded mins
// (mins computed from ORIGINAL K values — R7 lesson).
template<class T, bool CAP>
__device__ __forceinline__ void crossRevMax(T K[8], int d, unsigned m, T& cap) {
    T q[8];
    #pragma unroll
    for (int r = 0; r < 8; r++) q[r] = __shfl_xor_sync(m, K[7 - r], d);
    #pragma unroll
    for (int r = 0; r < 8; r++) {
        if (CAP) cap = vmax(cap, vmin(K[r], q[r]));
        K[r] = vmax(K[r], q[r]);
    }
}

template<class T> __device__ __forceinline__ void crossPred(T K[8], int d, bool km, unsigned m) {
    #pragma unroll
    for (int r = 0; r < 8; r++) {
        T q = __shfl_xor_sync(m, K[r], d);
        K[r] = km ? vmax(K[r], q) : vmin(K[r], q);
    }
}

// Top-16-of-64; lane s (in 8-lane group) holds 8 arbitrary tagged elements.
// Output: lane b=s&1 of each pair holds sorted positions 8b..8b+7.
// cap accumulates max over ALL discarded elements (both prunes).
template<class T, bool CAP>
__device__ __forceinline__ void top16net(T K[8], bool P1, unsigned m, T& cap) {
    sort8(K);
    crossRevPred(K, 1, P1, m);  bmerge8(K);
    crossRevMax<T,CAP>(K, 3, m, cap);
    crossPred(K, 1, P1, m);     bmerge8(K);
    crossRevMax<T,CAP>(K, 5, m, cap);
    crossPred(K, 1, P1, m);     bmerge8(K);
}

__device__ __forceinline__ unsigned norm_key(float a, float b, float c, unsigned tag) {
    float n = __fadd_rn(__fadd_rn(__fmul_rn(a, a), __fmul_rn(b, b)), __fmul_rn(c, c));
    return (__float_as_uint(n) & 0xFFFFFFC0u) | tag;
}

// gather one 3-float vector: 1 LDG.64 + 1 LDG.32 (8B-aligned split by parity)
__device__ __forceinline__ void gather_vec(const float* __restrict__ xrow, int idx,
                                           float& a, float& b, float& c) {
    bool odd = (idx & 1);
    int e = 3 * idx + (odd ? 1 : 0);
    int o = odd ? 3 * idx : 3 * idx + 2;
    float2 f2 = *(const float2*)(xrow + e);
    float  f1 = xrow[o];
    a = odd ? f1   : f2.x;
    b = odd ? f2.x : f2.y;
    c = odd ? f2.y : f1;
}

__global__ __launch_bounds__(TPB, 8)
void vns_kernel(const float* __restrict__ x, float* __restrict__ out) {
    const int lane = threadIdx.x & 31;
    const int s    = lane & 7;                         // sublane within row group
    const int row  = blockIdx.x * ROWS_PER_BLOCK + (threadIdx.x >> 5) * 4 + (lane >> 3);
    const bool P1  = (s & 1) == 0;
    const int  b   = s & 1;
    const int  q   = s >> 1;                           // 0..3

    // ---- loads: two 12-float chunks (3 consecutive float4) at 48B lane stride ----
    // lane owns vectors {4s..4s+3} and {4s+32..4s+35}; each LDG.128 touches only
    // 3 lines per 8-lane row group (vs ~6 with the old 96B-contiguous layout).
    const float* __restrict__ xrow = x + (size_t)row * 192;
    const float4* c0 = (const float4*)xrow + 3 * s;         // vectors 4s..4s+3
    const float4* c1 = (const float4*)xrow + 3 * s + 24;    // vectors 4s+32..4s+35
    const unsigned tA = 63 - 4 * s;                         // tags chunk0
    const unsigned tB = 31 - 4 * s;                         // tags chunk1 (63-(4s+32))
    unsigned K[8];
    {
        float4 r0 = c0[0], r1 = c0[1], r2 = c0[2];
        K[0] = norm_key(r0.x, r0.y, r0.z, tA    );
        K[1] = norm_key(r0.w, r1.x, r1.y, tA - 1);
        K[2] = norm_key(r1.z, r1.w, r2.x, tA - 2);
        K[3] = norm_key(r2.y, r2.z, r2.w, tA - 3);
        float4 r3 = c1[0], r4 = c1[1], r5 = c1[2];
        K[4] = norm_key(r3.x, r3.y, r3.z, tB    );
        K[5] = norm_key(r3.w, r4.x, r4.y, tB - 1);
        K[6] = norm_key(r4.z, r4.w, r5.x, tB - 2);
        K[7] = norm_key(r5.y, r5.z, r5.w, tB - 3);
    }

    unsigned cap = 0;
    top16net<unsigned, true>(K, P1, 0xffffffffu, cap);
    // key16 = true 17th-largest trunc-key: max of all discarded over the 8-lane group
    unsigned key16 = cap;
    key16 = vmax(key16, __shfl_xor_sync(0xffffffffu, key16, 1));
    key16 = vmax(key16, __shfl_xor_sync(0xffffffffu, key16, 2));
    key16 = vmax(key16, __shfl_xor_sync(0xffffffffu, key16, 4));

    // ---- exactness checks: adjacent trunc-equal over sorted positions 0..16 ----
    bool bad = false;
    #pragma unroll
    for (int r = 0; r < 7; r++) bad |= (((K[r] ^ K[r + 1]) >> 6) == 0);
    unsigned nb = __shfl_xor_sync(0xffffffffu, K[0], 1);
    unsigned bcmp = b ? key16 : nb;                        // b=0: pos7 vs pos8; b=1: pos15 vs key16
    bad |= (((K[7] ^ bcmp) >> 6) == 0);
    unsigned bal = __ballot_sync(0xffffffffu, bad);
    bool groupBad = ((bal >> (lane & 24)) & 0xFFu) != 0;

    int idx0, idx1;
    if (!groupBad) {
        unsigned t0 = (q & 1) ? K[2] : K[0];
        unsigned t1 = (q & 1) ? K[6] : K[4];
        unsigned Kp0 = (q & 2) ? t1 : t0;
        unsigned u0 = (q & 1) ? K[3] : K[1];
        unsigned u1 = (q & 1) ? K[7] : K[5];
        unsigned Kp1 = (q & 2) ? u1 : u0;
        idx0 = 63 - (int)(Kp0 & 63u);
        idx1 = 63 - (int)(Kp1 & 63u);
    } else {
        // ---- exact fallback (rare): re-read chunks, 64-bit (norm, idx) keys ----
        const unsigned gm = 0xFFu << (lane & 24);
        float4 r0 = c0[0], r1 = c0[1], r2 = c0[2];
        float4 r3 = c1[0], r4 = c1[1], r5 = c1[2];
        float N[8];
        N[0] = __fadd_rn(__fadd_rn(__fmul_rn(r0.x,r0.x), __fmul_rn(r0.y,r0.y)), __fmul_rn(r0.z,r0.z));
        N[1] = __fadd_rn(__fadd_rn(__fmul_rn(r0.w,r0.w), __fmul_rn(r1.x,r1.x)), __fmul_rn(r1.y,r1.y));
        N[2] = __fadd_rn(__fadd_rn(__fmul_rn(r1.z,r1.z), __fmul_rn(r1.w,r1.w)), __fmul_rn(r2.x,r2.x));
        N[3] = __fadd_rn(__fadd_rn(__fmul_rn(r2.y,r2.y), __fmul_rn(r2.z,r2.z)), __fmul_rn(r2.w,r2.w));
        N[4] = __fadd_rn(__fadd_rn(__fmul_rn(r3.x,r3.x), __fmul_rn(r3.y,r3.y)), __fmul_rn(r3.z,r3.z));
        N[5] = __fadd_rn(__fadd_rn(__fmul_rn(r3.w,r3.w), __fmul_rn(r4.x,r4.x)), __fmul_rn(r4.y,r4.y));
        N[6] = __fadd_rn(__fadd_rn(__fmul_rn(r4.z,r4.z), __fmul_rn(r4.w,r4.w)), __fmul_rn(r5.x,r5.x));
        N[7] = __fadd_rn(__fadd_rn(__fmul_rn(r5.y,r5.y), __fmul_rn(r5.z,r5.z)), __fmul_rn(r5.w,r5.w));
        unsigned long long A[8], dcap = 0;
        #pragma unroll
        for (int j = 0; j < 4; j++)
            A[j] = ((unsigned long long)__float_as_uint(N[j]) << 32) | (unsigned long long)(tA - j);
        #pragma unroll
        for (int j = 0; j < 4; j++)
            A[4 + j] = ((unsigned long long)__float_as_uint(N[4 + j]) << 32) | (unsigned long long)(tB - j);
        top16net<unsigned long long, false>(A, P1, gm, dcap);
        unsigned long long t0 = (q & 1) ? A[2] : A[0];
        unsigned long long t1 = (q & 1) ? A[6] : A[4];
        unsigned long long Kp0 = (q & 2) ? t1 : t0;
        unsigned long long u0 = (q & 1) ? A[3] : A[1];
        unsigned long long u1 = (q & 1) ? A[7] : A[5];
        unsigned long long Kp1 = (q & 2) ? u1 : u0;
        idx0 = 63 - (int)(Kp0 & 63ull);
        idx1 = 63 - (int)(Kp1 & 63ull);
    }

    // ---- gather: 2 instrs per vector (LDG.64 + LDG.32), L1-resident lines ----
    float a, bb, c, d, e, f;
    gather_vec(xrow, idx0, a, bb, c);
    gather_vec(xrow, idx1, d, e, f);

    // ---- store positions p0, p0+1 as 3 x STG.64 (8B-aligned: p0 even) ----
    const int p0 = 8 * b + 2 * q;
    float2* o2 = (float2*)(out + (size_t)row * 48 + 3 * p0);
    o2[0] = make_float2(a, bb);
    o2[1] = make_float2(c, d);
    o2[2] = make_float2(e, f);
}

extern "C" void kernel_launch(void* const* d_in, const int* in_sizes, int n_in,
                              void* d_out, int out_size) {
    const float* x = (const float*)d_in[0];
    float* out = (float*)d_out;
    vns_kernel<<<NROWS / ROWS_PER_BLOCK, TPB>>>(x, out);
}